// round 10
// baseline (speedup 1.0000x reference)
#include <cuda_runtime.h>
#include <cuda_bf16.h>
#include <cstdint>
#include <cstddef>

#define B_    4096
#define T_    128
#define NL_   256
#define NS_   64
#define NO_   32
#define V_    64
#define ROWS_ 32
#define GRID_ 128
#define NTH_  256

// smem byte offsets
#define OFF_SEQ   0          // 128 ints
#define OFF_SB1   512        // 256 f32
#define OFF_SB2   1536       // 2 x 32 f32 (parity)
#define OFF_SIDX  1792       // 2 x 32 int (parity)
#define OFF_YLOG  2048       // 32*36 f32 = 4608
#define OFF_YB    6656       // 32*68 f32 = 8704
#define OFF_X0H   15360      // 32*528
#define OFF_X0L   32256
#define OFF_X1H   49152
#define OFF_X1L   66048
#define OFF_W2H   82944      // 32*528
#define OFF_W2L   99840
#define OFF_W1    116736     // 8 warps * 2 bufs * 5120
#define SMEM_TOTAL 198656

#define XPB    528           // x / W2 plane pitch (bytes)
#define XLOFF  16896u        // lo-plane offset from hi-plane (both X and W2)
#define W1PB   80
#define W1PLANE 2560
#define W1BUF   5120
#define W1WARP  10240

__device__ __nv_bfloat16 g_W1h[(size_t)NS_ * NL_ * NL_];
__device__ __nv_bfloat16 g_W1l[(size_t)NS_ * NL_ * NL_];
__device__ __nv_bfloat16 g_W2h[(size_t)NS_ * NO_ * NL_];
__device__ __nv_bfloat16 g_W2l[(size_t)NS_ * NO_ * NL_];

__device__ __forceinline__ void cp16g(uint32_t dst, const void* src) {
    asm volatile("cp.async.cg.shared.global [%0], [%1], 16;" :: "r"(dst), "l"(src) : "memory");
}
#define CPCOMMIT() asm volatile("cp.async.commit_group;" ::: "memory")
#define CPWAIT0()  asm volatile("cp.async.wait_group 0;" ::: "memory")
#define CPWAIT1()  asm volatile("cp.async.wait_group 1;" ::: "memory")
#define CPWAIT2()  asm volatile("cp.async.wait_group 2;" ::: "memory")

__device__ __forceinline__ void ldm4(uint32_t a, uint32_t* r) {
    asm volatile("ldmatrix.sync.aligned.m8n8.x4.shared.b16 {%0,%1,%2,%3}, [%4];"
                 : "=r"(r[0]), "=r"(r[1]), "=r"(r[2]), "=r"(r[3]) : "r"(a));
}
__device__ __forceinline__ void ldm2(uint32_t a, uint32_t& r0, uint32_t& r1) {
    asm volatile("ldmatrix.sync.aligned.m8n8.x2.shared.b16 {%0,%1}, [%2];"
                 : "=r"(r0), "=r"(r1) : "r"(a));
}
__device__ __forceinline__ void mma16816(float* d, const uint32_t* a, uint32_t b0, uint32_t b1) {
    asm volatile("mma.sync.aligned.m16n8k16.row.col.f32.bf16.bf16.f32 "
                 "{%0,%1,%2,%3}, {%4,%5,%6,%7}, {%8,%9}, {%0,%1,%2,%3};"
                 : "+f"(d[0]), "+f"(d[1]), "+f"(d[2]), "+f"(d[3])
                 : "r"(a[0]), "r"(a[1]), "r"(a[2]), "r"(a[3]), "r"(b0), "r"(b1));
}
__device__ __forceinline__ float tanh_acc(float x) {
    float xc = fminf(fmaxf(x, -15.f), 15.f);
    float e = __expf(2.f * xc);
    return __fdividef(e - 1.f, e + 1.f);
}
__device__ __forceinline__ void pack2(float f0, float f1, uint32_t& hp, uint32_t& lp) {
    asm("cvt.rn.bf16x2.f32 %0, %1, %2;" : "=r"(hp) : "f"(f1), "f"(f0));
    float h0 = __uint_as_float(hp << 16);
    float h1 = __uint_as_float(hp & 0xffff0000u);
    asm("cvt.rn.bf16x2.f32 %0, %1, %2;" : "=r"(lp) : "f"(f1 - h1), "f"(f0 - h0));
}

// Per-warp W1 slice stage: warp w stages its 32 n-rows x 32 k (hi+lo) of chunk ck.
__device__ __forceinline__ void stage_w1_warp(uint32_t s0, int w, int buf, int s, int ck, int lane) {
    uint32_t base = s0 + OFF_W1 + (uint32_t)(w * W1WARP + buf * W1BUF);
    #pragma unroll
    for (int q = 0; q < 8; ++q) {
        int idx = q * 32 + lane;          // 0..255
        int pl = idx >> 7;
        int rem = idx & 127;
        int n = rem >> 2, slot = rem & 3;
        uint32_t d = base + (uint32_t)(pl * W1PLANE + n * W1PB + slot * 16);
        const __nv_bfloat16* p = (pl ? g_W1l : g_W1h)
                               + (size_t)(s * NL_ + w * 32 + n) * NL_ + ck * 32 + slot * 8;
        cp16g(d, p);
    }
    CPCOMMIT();
}
// Stage W2[s] hi+lo (CTA-wide, 2048 cp16).
__device__ __forceinline__ void stage_w2(uint32_t s0, int s, int tid) {
    #pragma unroll
    for (int q = 0; q < 8; ++q) {
        int g = tid + NTH_ * q;
        int pl = g >> 10;
        int rem = g & 1023;
        int n = rem >> 5, slot = rem & 31;
        uint32_t d = s0 + (uint32_t)(OFF_W2H + pl * XLOFF + n * XPB + slot * 16);
        const __nv_bfloat16* p = (pl ? g_W2l : g_W2h) + (size_t)(s * NO_ + n) * NL_ + slot * 8;
        cp16g(d, p);
    }
    CPCOMMIT();
}

__global__ void cvt_kernel(const float* __restrict__ W1, const float* __restrict__ W2) {
    size_t i = (size_t)blockIdx.x * blockDim.x + threadIdx.x;
    if (i < (size_t)NS_ * NL_ * NL_) {
        float x = W1[i];
        __nv_bfloat16 h = __float2bfloat16(x);
        g_W1h[i] = h;
        g_W1l[i] = __float2bfloat16(x - __bfloat162float(h));
    }
    if (i < (size_t)NS_ * NO_ * NL_) {
        float x = W2[i];
        __nv_bfloat16 h = __float2bfloat16(x);
        g_W2h[i] = h;
        g_W2l[i] = __float2bfloat16(x - __bfloat162float(h));
    }
}

__global__ __launch_bounds__(NTH_, 1)
void lalr_hmma_kernel(const float* __restrict__ latent0,
                      const float* __restrict__ b1,
                      const float* __restrict__ b2,
                      const int*   __restrict__ state_seq,
                      const int*   __restrict__ out_idx,
                      float*       __restrict__ out)
{
    extern __shared__ char smc[];
    const uint32_t s0 = (uint32_t)__cvta_generic_to_shared(smc);
    const int tid  = threadIdx.x;
    const int w    = tid >> 5;
    const int lane = tid & 31;
    const int r0   = blockIdx.x * ROWS_;

    int*   seq  = (int*)(smc + OFF_SEQ);
    float* sb1  = (float*)(smc + OFF_SB1);
    float* ylog = (float*)(smc + OFF_YLOG);   // pitch 36 floats
    float* yb   = (float*)(smc + OFF_YB);     // pitch 68 floats

    const int wn    = w * 32;
    const int mrow2 = (w & 1) * 16;
    const int nb2   = (w >> 1) * 8;

    const int a_row = (lane & 7) + ((lane >> 3) & 1) * 8;
    const int a_kof = (lane >> 4) * 8;
    const int b_row = (lane & 7) + ((lane >> 4) & 1) * 8;
    const int b_kof = ((lane >> 3) & 1) * 8;

    if (tid < T_) seq[tid] = state_seq[tid];

    // initial latent -> X0 planes (bf16 hi/lo)
    {
        int r = tid >> 3;
        int cb = (tid & 7) * 32;
        const float2* src = (const float2*)(latent0 + (size_t)(r0 + r) * NL_ + cb);
        #pragma unroll
        for (int i = 0; i < 16; ++i) {
            float2 f = src[i];
            uint32_t hp, lp;
            pack2(f.x, f.y, hp, lp);
            *(uint32_t*)(smc + OFF_X0H + r * XPB + (cb + 2 * i) * 2) = hp;
            *(uint32_t*)(smc + OFF_X0H + XLOFF + r * XPB + (cb + 2 * i) * 2) = lp;
        }
    }
    {
        int sfirst = state_seq[0];
        stage_w1_warp(s0, w, 0, sfirst, 0, lane);
        stage_w1_warp(s0, w, 1, sfirst, 1, lane);
    }
    __syncthreads();

    uint32_t xc = OFF_X0H;   // current x (hi plane; lo at +XLOFF)
    uint32_t xn = OFF_X1H;   // next x

    for (int t = 0; t < T_; ++t) {
        const int s = seq[t];
        const int par = t & 1;
        float* sb2p  = (float*)(smc + OFF_SB2)  + par * 32;
        int*   sidxp = (int*)(smc + OFF_SIDX)   + par * 32;

        sb1[tid] = b1[s * NL_ + tid];
        if (tid < NO_) { sb2p[tid] = b2[s * NO_ + tid]; sidxp[tid] = out_idx[s * NO_ + tid]; }
        stage_w2(s0, s, tid);

        // -------- Phase 1: x @ W1^T, per-warp ring, no CTA barriers --------
        float acc[2][4][4];
        #pragma unroll
        for (int mt = 0; mt < 2; ++mt)
            #pragma unroll
            for (int q = 0; q < 4; ++q)
                #pragma unroll
                for (int i = 0; i < 4; ++i) acc[mt][q][i] = 0.f;

        const uint32_t wbase = s0 + OFF_W1 + (uint32_t)(w * W1WARP);

        #pragma unroll
        for (int c = 0; c < 8; ++c) {
            if (c < 2)      CPWAIT2();
            else if (c < 7) CPWAIT1();
            else            CPWAIT0();
            __syncwarp();

            const uint32_t wb = wbase + (uint32_t)((c & 1) * W1BUF);

            #pragma unroll
            for (int ks = 0; ks < 2; ++ks) {
                int gk = c * 32 + ks * 16;
                int ck2 = ks * 16;
                uint32_t ah[2][4], al[2][4];
                ldm4(s0 + xc + (uint32_t)(a_row * XPB + (gk + a_kof) * 2), ah[0]);
                ldm4(s0 + xc + (uint32_t)((16 + a_row) * XPB + (gk + a_kof) * 2), ah[1]);
                ldm4(s0 + xc + XLOFF + (uint32_t)(a_row * XPB + (gk + a_kof) * 2), al[0]);
                ldm4(s0 + xc + XLOFF + (uint32_t)((16 + a_row) * XPB + (gk + a_kof) * 2), al[1]);
                #pragma unroll
                for (int p = 0; p < 2; ++p) {
                    uint32_t bh[4], bl[4];
                    uint32_t baddr = wb + (uint32_t)((p * 16 + b_row) * W1PB + (ck2 + b_kof) * 2);
                    ldm4(baddr, bh);
                    ldm4(baddr + W1PLANE, bl);
                    #pragma unroll
                    for (int mt = 0; mt < 2; ++mt) {
                        mma16816(acc[mt][2 * p],     ah[mt], bh[0], bh[1]);
                        mma16816(acc[mt][2 * p],     al[mt], bh[0], bh[1]);
                        mma16816(acc[mt][2 * p],     ah[mt], bl[0], bl[1]);
                        mma16816(acc[mt][2 * p + 1], ah[mt], bh[2], bh[3]);
                        mma16816(acc[mt][2 * p + 1], al[mt], bh[2], bh[3]);
                        mma16816(acc[mt][2 * p + 1], ah[mt], bl[2], bl[3]);
                    }
                }
            }

            if (c < 6) {
                stage_w1_warp(s0, w, c & 1, s, c + 2, lane);
            } else if (c == 7) {
                int sn = (t < T_ - 1) ? seq[t + 1] : s;
                stage_w1_warp(s0, w, 0, sn, 0, lane);
                stage_w1_warp(s0, w, 1, sn, 1, lane);
            }
        }

        // -------- Epilogue 1 (no CTA barrier): tanh(acc + b1) -> xn planes --------
        // Writes only this warp's n-columns; sb1 cols wn..wn+31 were written by
        // this warp's own lanes (tid == wn+lane), ordered by the loop's syncwarps.
        {
            int rowa = lane >> 2;
            #pragma unroll
            for (int mt = 0; mt < 2; ++mt) {
                #pragma unroll
                for (int q = 0; q < 4; ++q) {
                    int colb = wn + q * 8 + 2 * (lane & 3);
                    float2 bb = *(const float2*)(sb1 + colb);
                    int ra = mt * 16 + rowa;
                    uint32_t hp, lp;
                    pack2(tanh_acc(acc[mt][q][0] + bb.x), tanh_acc(acc[mt][q][1] + bb.y), hp, lp);
                    *(uint32_t*)(smc + xn + ra * XPB + colb * 2) = hp;
                    *(uint32_t*)(smc + xn + XLOFF + ra * XPB + colb * 2) = lp;
                    pack2(tanh_acc(acc[mt][q][2] + bb.x), tanh_acc(acc[mt][q][3] + bb.y), hp, lp);
                    *(uint32_t*)(smc + xn + (ra + 8) * XPB + colb * 2) = hp;
                    *(uint32_t*)(smc + xn + XLOFF + (ra + 8) * XPB + colb * 2) = lp;
                }
            }
        }
        __syncthreads();   // BAR_B: x_new complete + W2 stage published

        // -------- Phase 2: logits = x_new @ W2^T, 3 independent MMA chains --------
        {
            float aHH[4] = {0.f,0.f,0.f,0.f};
            float aLH[4] = {0.f,0.f,0.f,0.f};
            float aHL[4] = {0.f,0.f,0.f,0.f};
            #pragma unroll
            for (int ks = 0; ks < 16; ++ks) {
                int gk = ks * 16;
                uint32_t ah[4], al[4];
                ldm4(s0 + xn + (uint32_t)((mrow2 + a_row) * XPB + (gk + a_kof) * 2), ah);
                ldm4(s0 + xn + XLOFF + (uint32_t)((mrow2 + a_row) * XPB + (gk + a_kof) * 2), al);
                uint32_t baddr = s0 + (uint32_t)(OFF_W2H
                               + (nb2 + (lane & 7)) * XPB + (gk + ((lane >> 3) & 1) * 8) * 2);
                uint32_t bh0, bh1, bl0, bl1;
                ldm2(baddr, bh0, bh1);
                ldm2(baddr + XLOFF, bl0, bl1);
                mma16816(aHH, ah, bh0, bh1);
                mma16816(aLH, al, bh0, bh1);
                mma16816(aHL, ah, bl0, bl1);
            }
            int rowa = mrow2 + (lane >> 2);
            int colb = nb2 + 2 * (lane & 3);
            *(float2*)(ylog + rowa * 36 + colb) =
                make_float2(aHH[0] + aLH[0] + aHL[0], aHH[1] + aLH[1] + aHL[1]);
            *(float2*)(ylog + (rowa + 8) * 36 + colb) =
                make_float2(aHH[2] + aLH[2] + aHL[2], aHH[3] + aLH[3] + aHL[3]);
        }
        __syncthreads();   // BAR_C: logits visible

        // -------- Output path: 4 lanes/warp, each privately owns one row --------
        if (lane < 4) {
            int r = w * 4 + lane;
            float lg[32];
            float m = -1e30f;
            #pragma unroll
            for (int o = 0; o < 32; ++o) {
                lg[o] = ylog[r * 36 + o] + sb2p[o];
                m = fmaxf(m, lg[o]);
            }
            float ssum = 0.f;
            #pragma unroll
            for (int o = 0; o < 32; ++o) { lg[o] = __expf(lg[o] - m); ssum += lg[o]; }
            float inv = __frcp_rn(ssum);
            float* yrow = yb + r * 68;
            #pragma unroll
            for (int q4 = 0; q4 < 16; ++q4)
                *(float4*)(yrow + 4 * q4) = make_float4(0.f, 0.f, 0.f, 0.f);
            #pragma unroll
            for (int o = 0; o < 32; ++o)
                yrow[sidxp[o]] = lg[o] * inv;         // ascending o -> last wins
            float* orow = out + ((size_t)(r0 + r) * T_ + t) * V_;
            #pragma unroll
            for (int q4 = 0; q4 < 16; ++q4)
                *(float4*)(orow + 4 * q4) = *(const float4*)(yrow + 4 * q4);
        }
        // no trailing barrier: yb/out rows lane-private; ylog rewritten only after
        // next BAR_B; sb2/sidx parity-double-buffered.

        uint32_t tmp = xc; xc = xn; xn = tmp;
    }
}

extern "C" void kernel_launch(void* const* d_in, const int* in_sizes, int n_in,
                              void* d_out, int out_size)
{
    const float* latent0   = (const float*)d_in[0];
    const float* W1        = (const float*)d_in[1];
    const float* b1        = (const float*)d_in[2];
    const float* W2        = (const float*)d_in[3];
    const float* b2        = (const float*)d_in[4];
    const int*   state_seq = (const int*)  d_in[5];
    const int*   out_idx   = (const int*)  d_in[6];
    float*       out       = (float*)      d_out;

    cvt_kernel<<<(int)(((size_t)NS_ * NL_ * NL_ + 255) / 256), 256>>>(W1, W2);

    cudaFuncSetAttribute(lalr_hmma_kernel,
                         cudaFuncAttributeMaxDynamicSharedMemorySize, SMEM_TOTAL);
    lalr_hmma_kernel<<<GRID_, NTH_, SMEM_TOTAL>>>(latent0, b1, b2, state_seq, out_idx, out);
}

// round 11
// speedup vs baseline: 1.0114x; 1.0114x over previous
#include <cuda_runtime.h>
#include <cuda_bf16.h>
#include <cstdint>
#include <cstddef>

#define B_    4096
#define T_    128
#define NL_   256
#define NS_   64
#define NO_   32
#define V_    64
#define ROWS_ 32
#define GRID_ 128
#define NTH_  512

// smem byte offsets
#define OFF_SEQ   0          // 128 ints
#define OFF_SB2   512        // 2 x 32 f32 (parity)
#define OFF_SIDX  768        // 2 x 32 int (parity)
#define OFF_YLOG  1024       // 32*36 f32 = 4608
#define OFF_YB    5632       // 32*68 f32 = 8704
#define OFF_X0H   14336      // hi plane 16896; lo at +XLOFF
#define OFF_X1H   48128
#define OFF_W2H   81920
#define OFF_W1    115712     // 16 warps * 2 bufs * 2560
#define SMEM_TOTAL 197632

#define XPB    528           // x / W2 plane pitch (bytes)
#define XLOFF  16896u
#define W1PB   80            // W1 row pitch (bytes)
#define W1PLANE 1280         // 16 rows * 80
#define W1BUF   2560         // hi+lo
#define W1WARP  5120         // 2 buffers

__device__ __nv_bfloat16 g_W1h[(size_t)NS_ * NL_ * NL_];
__device__ __nv_bfloat16 g_W1l[(size_t)NS_ * NL_ * NL_];
__device__ __nv_bfloat16 g_W2h[(size_t)NS_ * NO_ * NL_];
__device__ __nv_bfloat16 g_W2l[(size_t)NS_ * NO_ * NL_];

__device__ __forceinline__ void cp16g(uint32_t dst, const void* src) {
    asm volatile("cp.async.cg.shared.global [%0], [%1], 16;" :: "r"(dst), "l"(src) : "memory");
}
#define CPCOMMIT() asm volatile("cp.async.commit_group;" ::: "memory")
#define CPWAIT0()  asm volatile("cp.async.wait_group 0;" ::: "memory")
#define CPWAIT1()  asm volatile("cp.async.wait_group 1;" ::: "memory")
#define CPWAIT2()  asm volatile("cp.async.wait_group 2;" ::: "memory")

__device__ __forceinline__ void ldm4(uint32_t a, uint32_t* r) {
    asm volatile("ldmatrix.sync.aligned.m8n8.x4.shared.b16 {%0,%1,%2,%3}, [%4];"
                 : "=r"(r[0]), "=r"(r[1]), "=r"(r[2]), "=r"(r[3]) : "r"(a));
}
__device__ __forceinline__ void ldm2(uint32_t a, uint32_t& r0, uint32_t& r1) {
    asm volatile("ldmatrix.sync.aligned.m8n8.x2.shared.b16 {%0,%1}, [%2];"
                 : "=r"(r0), "=r"(r1) : "r"(a));
}
__device__ __forceinline__ void mma16816(float* d, const uint32_t* a, uint32_t b0, uint32_t b1) {
    asm volatile("mma.sync.aligned.m16n8k16.row.col.f32.bf16.bf16.f32 "
                 "{%0,%1,%2,%3}, {%4,%5,%6,%7}, {%8,%9}, {%0,%1,%2,%3};"
                 : "+f"(d[0]), "+f"(d[1]), "+f"(d[2]), "+f"(d[3])
                 : "r"(a[0]), "r"(a[1]), "r"(a[2]), "r"(a[3]), "r"(b0), "r"(b1));
}
__device__ __forceinline__ float tanh_acc(float x) {
    float xc = fminf(fmaxf(x, -15.f), 15.f);
    float e = __expf(2.f * xc);
    return __fdividef(e - 1.f, e + 1.f);
}
__device__ __forceinline__ void pack2(float f0, float f1, uint32_t& hp, uint32_t& lp) {
    asm("cvt.rn.bf16x2.f32 %0, %1, %2;" : "=r"(hp) : "f"(f1), "f"(f0));
    float h0 = __uint_as_float(hp << 16);
    float h1 = __uint_as_float(hp & 0xffff0000u);
    asm("cvt.rn.bf16x2.f32 %0, %1, %2;" : "=r"(lp) : "f"(f1 - h1), "f"(f0 - h0));
}

// Per-warp W1 slice: warp w stages its 16 n-rows x 32 k (hi+lo) of chunk ck.
// 128 x 16B granules -> 4 per lane.
__device__ __forceinline__ void stage_w1_warp(uint32_t s0, int w, int buf, int s, int ck, int lane) {
    uint32_t base = s0 + OFF_W1 + (uint32_t)(w * W1WARP + buf * W1BUF);
    #pragma unroll
    for (int q = 0; q < 4; ++q) {
        int idx = q * 32 + lane;          // 0..127
        int pl = idx >> 6;
        int rem = idx & 63;
        int n = rem >> 2, slot = rem & 3;
        uint32_t d = base + (uint32_t)(pl * W1PLANE + n * W1PB + slot * 16);
        const __nv_bfloat16* p = (pl ? g_W1l : g_W1h)
                               + (size_t)(s * NL_ + w * 16 + n) * NL_ + ck * 32 + slot * 8;
        cp16g(d, p);
    }
    CPCOMMIT();
}
// Stage W2[s] hi+lo (CTA-wide, 2048 granules / 512 threads = 4 each).
__device__ __forceinline__ void stage_w2(uint32_t s0, int s, int tid) {
    #pragma unroll
    for (int q = 0; q < 4; ++q) {
        int g = tid + NTH_ * q;
        int pl = g >> 10;
        int rem = g & 1023;
        int n = rem >> 5, slot = rem & 31;
        uint32_t d = s0 + (uint32_t)(OFF_W2H + pl * XLOFF + n * XPB + slot * 16);
        const __nv_bfloat16* p = (pl ? g_W2l : g_W2h) + (size_t)(s * NO_ + n) * NL_ + slot * 8;
        cp16g(d, p);
    }
    CPCOMMIT();
}

__global__ void cvt_kernel(const float* __restrict__ W1, const float* __restrict__ W2) {
    size_t i = (size_t)blockIdx.x * blockDim.x + threadIdx.x;
    if (i < (size_t)NS_ * NL_ * NL_) {
        float x = W1[i];
        __nv_bfloat16 h = __float2bfloat16(x);
        g_W1h[i] = h;
        g_W1l[i] = __float2bfloat16(x - __bfloat162float(h));
    }
    if (i < (size_t)NS_ * NO_ * NL_) {
        float x = W2[i];
        __nv_bfloat16 h = __float2bfloat16(x);
        g_W2h[i] = h;
        g_W2l[i] = __float2bfloat16(x - __bfloat162float(h));
    }
}

__global__ __launch_bounds__(NTH_, 1)
void lalr_hmma_kernel(const float* __restrict__ latent0,
                      const float* __restrict__ b1,
                      const float* __restrict__ b2,
                      const int*   __restrict__ state_seq,
                      const int*   __restrict__ out_idx,
                      float*       __restrict__ out)
{
    extern __shared__ char smc[];
    const uint32_t s0 = (uint32_t)__cvta_generic_to_shared(smc);
    const int tid  = threadIdx.x;
    const int w    = tid >> 5;
    const int lane = tid & 31;
    const int r0   = blockIdx.x * ROWS_;

    int*   seq  = (int*)(smc + OFF_SEQ);
    float* ylog = (float*)(smc + OFF_YLOG);   // pitch 36 floats
    float* yb   = (float*)(smc + OFF_YB);     // pitch 68 floats

    const int wn    = w * 16;                 // phase-1 n-slice base
    const int mrow2 = (w & 1) * 16;           // phase-2 (warps 0-7)
    const int nb2   = (w >> 1) * 8;

    const int a_row = (lane & 7) + ((lane >> 3) & 1) * 8;
    const int a_kof = (lane >> 4) * 8;
    const int b_row = (lane & 7) + ((lane >> 4) & 1) * 8;
    const int b_kof = ((lane >> 3) & 1) * 8;

    if (tid < T_) seq[tid] = state_seq[tid];

    // initial latent -> X0 planes (bf16 hi/lo). 32 rows x 16 thr, 16 cols each.
    {
        int r = tid >> 4;
        int cb = (tid & 15) * 16;
        const float2* src = (const float2*)(latent0 + (size_t)(r0 + r) * NL_ + cb);
        #pragma unroll
        for (int i = 0; i < 8; ++i) {
            float2 f = src[i];
            uint32_t hp, lp;
            pack2(f.x, f.y, hp, lp);
            *(uint32_t*)(smc + OFF_X0H + r * XPB + (cb + 2 * i) * 2) = hp;
            *(uint32_t*)(smc + OFF_X0H + XLOFF + r * XPB + (cb + 2 * i) * 2) = lp;
        }
    }
    {
        int sfirst = state_seq[0];
        stage_w1_warp(s0, w, 0, sfirst, 0, lane);
        stage_w1_warp(s0, w, 1, sfirst, 1, lane);
    }
    __syncthreads();

    uint32_t xc = OFF_X0H;
    uint32_t xn = OFF_X1H;

    for (int t = 0; t < T_; ++t) {
        const int s = seq[t];
        const int par = t & 1;
        float* sb2p  = (float*)(smc + OFF_SB2)  + par * 32;
        int*   sidxp = (int*)(smc + OFF_SIDX)   + par * 32;

        if (tid < NO_) { sb2p[tid] = b2[s * NO_ + tid]; sidxp[tid] = out_idx[s * NO_ + tid]; }
        stage_w2(s0, s, tid);

        // -------- Phase 1: x @ W1^T, per-warp ring, term-major MMA order --------
        float acc[2][2][4];
        #pragma unroll
        for (int mt = 0; mt < 2; ++mt)
            #pragma unroll
            for (int nt = 0; nt < 2; ++nt)
                #pragma unroll
                for (int i = 0; i < 4; ++i) acc[mt][nt][i] = 0.f;

        const uint32_t wbase = s0 + OFF_W1 + (uint32_t)(w * W1WARP);

        #pragma unroll
        for (int c = 0; c < 8; ++c) {
            if (c < 2)      CPWAIT2();
            else if (c < 7) CPWAIT1();
            else            CPWAIT0();
            __syncwarp();

            const uint32_t wb = wbase + (uint32_t)((c & 1) * W1BUF);

            #pragma unroll
            for (int ks = 0; ks < 2; ++ks) {
                int gk = c * 32 + ks * 16;
                int ck2 = ks * 16;
                uint32_t ah[2][4], al[2][4];
                ldm4(s0 + xc + (uint32_t)(a_row * XPB + (gk + a_kof) * 2), ah[0]);
                ldm4(s0 + xc + (uint32_t)((16 + a_row) * XPB + (gk + a_kof) * 2), ah[1]);
                ldm4(s0 + xc + XLOFF + (uint32_t)(a_row * XPB + (gk + a_kof) * 2), al[0]);
                ldm4(s0 + xc + XLOFF + (uint32_t)((16 + a_row) * XPB + (gk + a_kof) * 2), al[1]);
                uint32_t bh[4], bl[4];
                uint32_t baddr = wb + (uint32_t)(b_row * W1PB + (ck2 + b_kof) * 2);
                ldm4(baddr, bh);
                ldm4(baddr + W1PLANE, bl);
                // term-major: same-acc reuse distance = 4 MMAs
                #pragma unroll
                for (int mt = 0; mt < 2; ++mt) {
                    mma16816(acc[mt][0], ah[mt], bh[0], bh[1]);
                    mma16816(acc[mt][1], ah[mt], bh[2], bh[3]);
                }
                #pragma unroll
                for (int mt = 0; mt < 2; ++mt) {
                    mma16816(acc[mt][0], al[mt], bh[0], bh[1]);
                    mma16816(acc[mt][1], al[mt], bh[2], bh[3]);
                }
                #pragma unroll
                for (int mt = 0; mt < 2; ++mt) {
                    mma16816(acc[mt][0], ah[mt], bl[0], bl[1]);
                    mma16816(acc[mt][1], ah[mt], bl[2], bl[3]);
                }
            }

            if (c < 6) {
                stage_w1_warp(s0, w, c & 1, s, c + 2, lane);
            } else if (c == 7) {
                int sn = (t < T_ - 1) ? seq[t + 1] : s;
                stage_w1_warp(s0, w, 0, sn, 0, lane);
                stage_w1_warp(s0, w, 1, sn, 1, lane);
            }
        }

        // -------- Epilogue 1 (no CTA barrier): tanh(acc + b1) -> xn planes --------
        {
            int rowa = lane >> 2;
            #pragma unroll
            for (int mt = 0; mt < 2; ++mt) {
                #pragma unroll
                for (int nt = 0; nt < 2; ++nt) {
                    int colb = wn + nt * 8 + 2 * (lane & 3);
                    float2 bb = __ldg((const float2*)(b1 + s * NL_ + colb));
                    int ra = mt * 16 + rowa;
                    uint32_t hp, lp;
                    pack2(tanh_acc(acc[mt][nt][0] + bb.x), tanh_acc(acc[mt][nt][1] + bb.y), hp, lp);
                    *(uint32_t*)(smc + xn + ra * XPB + colb * 2) = hp;
                    *(uint32_t*)(smc + xn + XLOFF + ra * XPB + colb * 2) = lp;
                    pack2(tanh_acc(acc[mt][nt][2] + bb.x), tanh_acc(acc[mt][nt][3] + bb.y), hp, lp);
                    *(uint32_t*)(smc + xn + (ra + 8) * XPB + colb * 2) = hp;
                    *(uint32_t*)(smc + xn + XLOFF + (ra + 8) * XPB + colb * 2) = lp;
                }
            }
        }
        __syncthreads();   // BAR_B: x_new complete + W2 stage published

        // -------- Phase 2 (warps 0-7): logits = x_new @ W2^T, 3 chains --------
        if (w < 8) {
            float aHH[4] = {0.f,0.f,0.f,0.f};
            float aLH[4] = {0.f,0.f,0.f,0.f};
            float aHL[4] = {0.f,0.f,0.f,0.f};
            #pragma unroll
            for (int ks = 0; ks < 16; ++ks) {
                int gk = ks * 16;
                uint32_t ah[4], al[4];
                ldm4(s0 + xn + (uint32_t)((mrow2 + a_row) * XPB + (gk + a_kof) * 2), ah);
                ldm4(s0 + xn + XLOFF + (uint32_t)((mrow2 + a_row) * XPB + (gk + a_kof) * 2), al);
                uint32_t baddr = s0 + (uint32_t)(OFF_W2H
                               + (nb2 + (lane & 7)) * XPB + (gk + ((lane >> 3) & 1) * 8) * 2);
                uint32_t bh0, bh1, bl0, bl1;
                ldm2(baddr, bh0, bh1);
                ldm2(baddr + XLOFF, bl0, bl1);
                mma16816(aHH, ah, bh0, bh1);
                mma16816(aLH, al, bh0, bh1);
                mma16816(aHL, ah, bl0, bl1);
            }
            int rowa = mrow2 + (lane >> 2);
            int colb = nb2 + 2 * (lane & 3);
            *(float2*)(ylog + rowa * 36 + colb) =
                make_float2(aHH[0] + aLH[0] + aHL[0], aHH[1] + aLH[1] + aHL[1]);
            *(float2*)(ylog + (rowa + 8) * 36 + colb) =
                make_float2(aHH[2] + aLH[2] + aHL[2], aHH[3] + aLH[3] + aHL[3]);
        }
        __syncthreads();   // BAR_C: logits visible

        // -------- Output path: 2 lanes/warp, each privately owns one row --------
        if (lane < 2) {
            int r = w * 2 + lane;
            float lg[32];
            float m = -1e30f;
            #pragma unroll
            for (int o = 0; o < 32; ++o) {
                lg[o] = ylog[r * 36 + o] + sb2p[o];
                m = fmaxf(m, lg[o]);
            }
            float ssum = 0.f;
            #pragma unroll
            for (int o = 0; o < 32; ++o) { lg[o] = __expf(lg[o] - m); ssum += lg[o]; }
            float inv = __frcp_rn(ssum);
            float* yrow = yb + r * 68;
            #pragma unroll
            for (int q4 = 0; q4 < 16; ++q4)
                *(float4*)(yrow + 4 * q4) = make_float4(0.f, 0.f, 0.f, 0.f);
            #pragma unroll
            for (int o = 0; o < 32; ++o)
                yrow[sidxp[o]] = lg[o] * inv;         // ascending o -> last wins
            float* orow = out + ((size_t)(r0 + r) * T_ + t) * V_;
            #pragma unroll
            for (int q4 = 0; q4 < 16; ++q4)
                *(float4*)(orow + 4 * q4) = *(const float4*)(yrow + 4 * q4);
        }
        // no trailing barrier: yb/out rows lane-private; ylog rewritten only after
        // next BAR_B; sb2/sidx parity-double-buffered.

        uint32_t tmp = xc; xc = xn; xn = tmp;
    }
}

extern "C" void kernel_launch(void* const* d_in, const int* in_sizes, int n_in,
                              void* d_out, int out_size)
{
    const float* latent0   = (const float*)d_in[0];
    const float* W1        = (const float*)d_in[1];
    const float* b1        = (const float*)d_in[2];
    const float* W2        = (const float*)d_in[3];
    const float* b2        = (const float*)d_in[4];
    const int*   state_seq = (const int*)  d_in[5];
    const int*   out_idx   = (const int*)  d_in[6];
    float*       out       = (float*)      d_out;

    cvt_kernel<<<(int)(((size_t)NS_ * NL_ * NL_ + 255) / 256), 256>>>(W1, W2);

    cudaFuncSetAttribute(lalr_hmma_kernel,
                         cudaFuncAttributeMaxDynamicSharedMemorySize, SMEM_TOTAL);
    lalr_hmma_kernel<<<GRID_, NTH_, SMEM_TOTAL>>>(latent0, b1, b2, state_seq, out_idx, out);
}

// round 12
// speedup vs baseline: 1.3269x; 1.3119x over previous
#include <cuda_runtime.h>
#include <cuda_bf16.h>
#include <cstdint>
#include <cstddef>

#define B_    4096
#define T_    128
#define NL_   256
#define NS_   64
#define NO_   32
#define V_    64
#define ROWS_ 32
#define GRID_ 128
#define NTH_  576      // 16 compute warps + 2 IO warps

// smem byte offsets
#define OFF_SEQ   0          // 128 ints
#define OFF_SB2   512        // 2 IO warps x 32 f32
#define OFF_SIDX  768        // 2 IO warps x 32 int
#define OFF_YLOG  1024       // 32*36 f32 = 4608
#define OFF_YB    5632       // 32*68 f32 = 8704
#define OFF_X0H   14336      // hi plane 16896; lo at +XLOFF
#define OFF_X1H   48128
#define OFF_W2H   81920
#define OFF_W1    115712     // 16 warps * 2 bufs * 2560
#define SMEM_TOTAL 197632

#define XPB    528           // x / W2 plane pitch (bytes)
#define XLOFF  16896u
#define W1PB   80            // W1 row pitch (bytes)
#define W1PLANE 1280         // 16 rows * 80
#define W1BUF   2560         // hi+lo
#define W1WARP  5120         // 2 buffers

__device__ __nv_bfloat16 g_W1h[(size_t)NS_ * NL_ * NL_];
__device__ __nv_bfloat16 g_W1l[(size_t)NS_ * NL_ * NL_];
__device__ __nv_bfloat16 g_W2h[(size_t)NS_ * NO_ * NL_];
__device__ __nv_bfloat16 g_W2l[(size_t)NS_ * NO_ * NL_];

__device__ __forceinline__ void cp16g(uint32_t dst, const void* src) {
    asm volatile("cp.async.cg.shared.global [%0], [%1], 16;" :: "r"(dst), "l"(src) : "memory");
}
#define CPCOMMIT() asm volatile("cp.async.commit_group;" ::: "memory")
#define CPWAIT0()  asm volatile("cp.async.wait_group 0;" ::: "memory")
#define CPWAIT1()  asm volatile("cp.async.wait_group 1;" ::: "memory")

__device__ __forceinline__ void ldm4(uint32_t a, uint32_t* r) {
    asm volatile("ldmatrix.sync.aligned.m8n8.x4.shared.b16 {%0,%1,%2,%3}, [%4];"
                 : "=r"(r[0]), "=r"(r[1]), "=r"(r[2]), "=r"(r[3]) : "r"(a));
}
__device__ __forceinline__ void mma16816(float* d, const uint32_t* a, uint32_t b0, uint32_t b1) {
    asm volatile("mma.sync.aligned.m16n8k16.row.col.f32.bf16.bf16.f32 "
                 "{%0,%1,%2,%3}, {%4,%5,%6,%7}, {%8,%9}, {%0,%1,%2,%3};"
                 : "+f"(d[0]), "+f"(d[1]), "+f"(d[2]), "+f"(d[3])
                 : "r"(a[0]), "r"(a[1]), "r"(a[2]), "r"(a[3]), "r"(b0), "r"(b1));
}
__device__ __forceinline__ float tanh_acc(float x) {
    float xc = fminf(fmaxf(x, -15.f), 15.f);
    float e = __expf(2.f * xc);
    return __fdividef(e - 1.f, e + 1.f);
}
__device__ __forceinline__ void pack2(float f0, float f1, uint32_t& hp, uint32_t& lp) {
    asm("cvt.rn.bf16x2.f32 %0, %1, %2;" : "=r"(hp) : "f"(f1), "f"(f0));
    float h0 = __uint_as_float(hp << 16);
    float h1 = __uint_as_float(hp & 0xffff0000u);
    asm("cvt.rn.bf16x2.f32 %0, %1, %2;" : "=r"(lp) : "f"(f1 - h1), "f"(f0 - h0));
}

// Per-warp W1 slice: compute warp w stages its 16 n-rows x 32 k (hi+lo) of chunk ck.
__device__ __forceinline__ void stage_w1_warp(uint32_t s0, int w, int buf, int s, int ck, int lane) {
    uint32_t base = s0 + OFF_W1 + (uint32_t)(w * W1WARP + buf * W1BUF);
    #pragma unroll
    for (int q = 0; q < 4; ++q) {
        int idx = q * 32 + lane;          // 0..127
        int pl = idx >> 6;
        int rem = idx & 63;
        int n = rem >> 2, slot = rem & 3;
        uint32_t d = base + (uint32_t)(pl * W1PLANE + n * W1PB + slot * 16);
        const __nv_bfloat16* p = (pl ? g_W1l : g_W1h)
                               + (size_t)(s * NL_ + w * 16 + n) * NL_ + ck * 32 + slot * 8;
        cp16g(d, p);
    }
    CPCOMMIT();
}
// Stage W2[s] hi+lo from the 2 IO warps (64 threads, 32 granules each).
__device__ __forceinline__ void stage_w2_io(uint32_t s0, int s, int tio) {
    #pragma unroll
    for (int q = 0; q < 32; ++q) {
        int g = tio + 64 * q;             // 0..2047
        int pl = g >> 10;
        int rem = g & 1023;
        int n = rem >> 5, slot = rem & 31;
        uint32_t d = s0 + (uint32_t)(OFF_W2H + pl * XLOFF + n * XPB + slot * 16);
        const __nv_bfloat16* p = (pl ? g_W2l : g_W2h) + (size_t)(s * NO_ + n) * NL_ + slot * 8;
        cp16g(d, p);
    }
    CPCOMMIT();
}

__global__ void cvt_kernel(const float* __restrict__ W1, const float* __restrict__ W2) {
    size_t i = (size_t)blockIdx.x * blockDim.x + threadIdx.x;
    if (i < (size_t)NS_ * NL_ * NL_) {
        float x = W1[i];
        __nv_bfloat16 h = __float2bfloat16(x);
        g_W1h[i] = h;
        g_W1l[i] = __float2bfloat16(x - __bfloat162float(h));
    }
    if (i < (size_t)NS_ * NO_ * NL_) {
        float x = W2[i];
        __nv_bfloat16 h = __float2bfloat16(x);
        g_W2h[i] = h;
        g_W2l[i] = __float2bfloat16(x - __bfloat162float(h));
    }
}

__global__ __launch_bounds__(NTH_, 1)
void lalr_hmma_kernel(const float* __restrict__ latent0,
                      const float* __restrict__ b1,
                      const float* __restrict__ b2,
                      const int*   __restrict__ state_seq,
                      const int*   __restrict__ out_idx,
                      float*       __restrict__ out)
{
    extern __shared__ char smc[];
    const uint32_t s0 = (uint32_t)__cvta_generic_to_shared(smc);
    const int tid  = threadIdx.x;
    const int w    = tid >> 5;
    const int lane = tid & 31;
    const int r0   = blockIdx.x * ROWS_;
    const bool is_io = (w >= 16);

    int*   seq  = (int*)(smc + OFF_SEQ);
    float* ylog = (float*)(smc + OFF_YLOG);   // pitch 36 floats
    float* yb   = (float*)(smc + OFF_YB);     // pitch 68 floats

    const int wn = w * 16;                    // compute warp n-slice base

    const int a_row = (lane & 7) + ((lane >> 3) & 1) * 8;
    const int a_kof = (lane >> 4) * 8;
    const int b_row = (lane & 7) + ((lane >> 4) & 1) * 8;
    const int b_kof = ((lane >> 3) & 1) * 8;

    if (tid < T_) seq[tid] = state_seq[tid];

    if (!is_io) {
        // initial latent -> X0 planes (bf16 hi/lo). 32 rows x 16 thr, 16 cols each.
        int r = tid >> 4;
        int cb = (tid & 15) * 16;
        const float2* src = (const float2*)(latent0 + (size_t)(r0 + r) * NL_ + cb);
        #pragma unroll
        for (int i = 0; i < 8; ++i) {
            float2 f = src[i];
            uint32_t hp, lp;
            pack2(f.x, f.y, hp, lp);
            *(uint32_t*)(smc + OFF_X0H + r * XPB + (cb + 2 * i) * 2) = hp;
            *(uint32_t*)(smc + OFF_X0H + XLOFF + r * XPB + (cb + 2 * i) * 2) = lp;
        }
        int sfirst = state_seq[0];
        stage_w1_warp(s0, w, 0, sfirst, 0, lane);
        stage_w1_warp(s0, w, 1, sfirst, 1, lane);
    } else {
        stage_w2_io(s0, state_seq[0], (w - 16) * 32 + lane);
    }
    __syncthreads();

    uint32_t xc = OFF_X0H;
    uint32_t xn = OFF_X1H;

    for (int t = 0; t < T_; ++t) {
        const int s = seq[t];

        if (!is_io) {
            // -------- Phase 1: x @ W1^T, per-warp ring, term-major MMA order ------
            float acc[2][2][4];
            #pragma unroll
            for (int mt = 0; mt < 2; ++mt)
                #pragma unroll
                for (int nt = 0; nt < 2; ++nt)
                    #pragma unroll
                    for (int i = 0; i < 4; ++i) acc[mt][nt][i] = 0.f;

            const uint32_t wbase = s0 + OFF_W1 + (uint32_t)(w * W1WARP);

            #pragma unroll
            for (int c = 0; c < 8; ++c) {
                if (c == 7) CPWAIT0(); else CPWAIT1();
                __syncwarp();

                const uint32_t wb = wbase + (uint32_t)((c & 1) * W1BUF);

                #pragma unroll
                for (int ks = 0; ks < 2; ++ks) {
                    int gk = c * 32 + ks * 16;
                    int ck2 = ks * 16;
                    uint32_t ah[2][4], al[2][4];
                    ldm4(s0 + xc + (uint32_t)(a_row * XPB + (gk + a_kof) * 2), ah[0]);
                    ldm4(s0 + xc + (uint32_t)((16 + a_row) * XPB + (gk + a_kof) * 2), ah[1]);
                    ldm4(s0 + xc + XLOFF + (uint32_t)(a_row * XPB + (gk + a_kof) * 2), al[0]);
                    ldm4(s0 + xc + XLOFF + (uint32_t)((16 + a_row) * XPB + (gk + a_kof) * 2), al[1]);
                    uint32_t bh[4], bl[4];
                    uint32_t baddr = wb + (uint32_t)(b_row * W1PB + (ck2 + b_kof) * 2);
                    ldm4(baddr, bh);
                    ldm4(baddr + W1PLANE, bl);
                    #pragma unroll
                    for (int mt = 0; mt < 2; ++mt) {
                        mma16816(acc[mt][0], ah[mt], bh[0], bh[1]);
                        mma16816(acc[mt][1], ah[mt], bh[2], bh[3]);
                    }
                    #pragma unroll
                    for (int mt = 0; mt < 2; ++mt) {
                        mma16816(acc[mt][0], al[mt], bh[0], bh[1]);
                        mma16816(acc[mt][1], al[mt], bh[2], bh[3]);
                    }
                    #pragma unroll
                    for (int mt = 0; mt < 2; ++mt) {
                        mma16816(acc[mt][0], ah[mt], bl[0], bl[1]);
                        mma16816(acc[mt][1], ah[mt], bl[2], bl[3]);
                    }
                }

                if (c < 6) {
                    stage_w1_warp(s0, w, c & 1, s, c + 2, lane);
                } else if (c == 7) {
                    int sn = (t < T_ - 1) ? seq[t + 1] : s;
                    stage_w1_warp(s0, w, 0, sn, 0, lane);
                    stage_w1_warp(s0, w, 1, sn, 1, lane);
                }
            }

            // Epilogue: tanh(acc + b1) -> xn planes (warp's own n-columns)
            {
                int rowa = lane >> 2;
                #pragma unroll
                for (int mt = 0; mt < 2; ++mt) {
                    #pragma unroll
                    for (int nt = 0; nt < 2; ++nt) {
                        int colb = wn + nt * 8 + 2 * (lane & 3);
                        float2 bb = __ldg((const float2*)(b1 + s * NL_ + colb));
                        int ra = mt * 16 + rowa;
                        uint32_t hp, lp;
                        pack2(tanh_acc(acc[mt][nt][0] + bb.x), tanh_acc(acc[mt][nt][1] + bb.y), hp, lp);
                        *(uint32_t*)(smc + xn + ra * XPB + colb * 2) = hp;
                        *(uint32_t*)(smc + xn + XLOFF + ra * XPB + colb * 2) = lp;
                        pack2(tanh_acc(acc[mt][nt][2] + bb.x), tanh_acc(acc[mt][nt][3] + bb.y), hp, lp);
                        *(uint32_t*)(smc + xn + (ra + 8) * XPB + colb * 2) = hp;
                        *(uint32_t*)(smc + xn + XLOFF + (ra + 8) * XPB + colb * 2) = lp;
                    }
                }
            }
        }
        __syncthreads();   // BAR: x_new complete, visible to everyone

        if (is_io) {
            // -------- IO warps: phase2 + softmax + scatter + store (overlaps next phase1)
            const int wio = w - 16;
            const int mb  = wio * 16;
            float* sb2p  = (float*)(smc + OFF_SB2)  + wio * 32;
            int*   sidxp = (int*)(smc + OFF_SIDX)   + wio * 32;
            sb2p[lane]  = b2[s * NO_ + lane];
            sidxp[lane] = out_idx[s * NO_ + lane];

            CPWAIT0();       // W2[s] resident (staged by these warps last step)
            __syncwarp();

            float acc[4][4];
            #pragma unroll
            for (int nt = 0; nt < 4; ++nt)
                #pragma unroll
                for (int i = 0; i < 4; ++i) acc[nt][i] = 0.f;

            #pragma unroll
            for (int ks = 0; ks < 16; ++ks) {
                int gk = ks * 16;
                uint32_t ah[4], al[4];
                ldm4(s0 + xn + (uint32_t)((mb + a_row) * XPB + (gk + a_kof) * 2), ah);
                ldm4(s0 + xn + XLOFF + (uint32_t)((mb + a_row) * XPB + (gk + a_kof) * 2), al);
                #pragma unroll
                for (int ns = 0; ns < 2; ++ns) {
                    uint32_t bh[4], bl[4];
                    uint32_t baddr = s0 + (uint32_t)(OFF_W2H
                                   + (ns * 16 + b_row) * XPB + (gk + b_kof) * 2);
                    ldm4(baddr, bh);
                    ldm4(baddr + XLOFF, bl);
                    mma16816(acc[2 * ns],     ah, bh[0], bh[1]);
                    mma16816(acc[2 * ns + 1], ah, bh[2], bh[3]);
                    mma16816(acc[2 * ns],     al, bh[0], bh[1]);
                    mma16816(acc[2 * ns + 1], al, bh[2], bh[3]);
                    mma16816(acc[2 * ns],     ah, bl[0], bl[1]);
                    mma16816(acc[2 * ns + 1], ah, bl[2], bl[3]);
                }
            }

            // Both IO warps' W2 reads done before restaging W2
            asm volatile("bar.sync 1, 64;" ::: "memory");

            // logits -> warp-private ylog rows
            {
                int rowa = mb + (lane >> 2);
                #pragma unroll
                for (int nt = 0; nt < 4; ++nt) {
                    int colb = nt * 8 + 2 * (lane & 3);
                    *(float2*)(ylog + rowa * 36 + colb)       = make_float2(acc[nt][0], acc[nt][1]);
                    *(float2*)(ylog + (rowa + 8) * 36 + colb) = make_float2(acc[nt][2], acc[nt][3]);
                }
            }
            __syncwarp();

            if (lane < 16) {
                int r = mb + lane;
                float lg[32];
                float m = -1e30f;
                #pragma unroll
                for (int o = 0; o < 32; ++o) {
                    lg[o] = ylog[r * 36 + o] + sb2p[o];
                    m = fmaxf(m, lg[o]);
                }
                float ssum = 0.f;
                #pragma unroll
                for (int o = 0; o < 32; ++o) { lg[o] = __expf(lg[o] - m); ssum += lg[o]; }
                float inv = __frcp_rn(ssum);
                float* yrow = yb + r * 68;
                #pragma unroll
                for (int q4 = 0; q4 < 16; ++q4)
                    *(float4*)(yrow + 4 * q4) = make_float4(0.f, 0.f, 0.f, 0.f);
                #pragma unroll
                for (int o = 0; o < 32; ++o)
                    yrow[sidxp[o]] = lg[o] * inv;      // ascending o -> last wins
                float* orow = out + ((size_t)(r0 + r) * T_ + t) * V_;
                #pragma unroll
                for (int q4 = 0; q4 < 16; ++q4)
                    *(float4*)(orow + 4 * q4) = *(const float4*)(yrow + 4 * q4);
            }

            // stage W2 for next step
            int sn = (t < T_ - 1) ? seq[t + 1] : s;
            stage_w2_io(s0, sn, wio * 32 + lane);
        }

        uint32_t tmp = xc; xc = xn; xn = tmp;
    }
}

extern "C" void kernel_launch(void* const* d_in, const int* in_sizes, int n_in,
                              void* d_out, int out_size)
{
    const float* latent0   = (const float*)d_in[0];
    const float* W1        = (const float*)d_in[1];
    const float* b1        = (const float*)d_in[2];
    const float* W2        = (const float*)d_in[3];
    const float* b2        = (const float*)d_in[4];
    const int*   state_seq = (const int*)  d_in[5];
    const int*   out_idx   = (const int*)  d_in[6];
    float*       out       = (float*)      d_out;

    cvt_kernel<<<(int)(((size_t)NS_ * NL_ * NL_ + 255) / 256), 256>>>(W1, W2);

    cudaFuncSetAttribute(lalr_hmma_kernel,
                         cudaFuncAttributeMaxDynamicSharedMemorySize, SMEM_TOTAL);
    lalr_hmma_kernel<<<GRID_, NTH_, SMEM_TOTAL>>>(latent0, b1, b2, state_seq, out_idx, out);
}

// round 13
// speedup vs baseline: 1.3607x; 1.0255x over previous
#include <cuda_runtime.h>
#include <cuda_bf16.h>
#include <cstdint>
#include <cstddef>

#define B_    4096
#define T_    128
#define NL_   256
#define NS_   64
#define NO_   32
#define V_    64
#define ROWS_ 32
#define GRID_ 128
#define NTH_  320      // 8 compute warps (m32n32) + 2 IO warps

// smem byte offsets
#define OFF_SEQ   0          // 128 ints
#define OFF_SB2   512        // 2 IO warps x 32 f32
#define OFF_SIDX  768        // 2 IO warps x 32 int
#define OFF_YLOG  1024       // 32*36 f32 = 4608
#define OFF_YB    5632       // 32*68 f32 = 8704
#define OFF_X0H   14336      // hi plane 16896; lo at +XLOFF
#define OFF_X1H   48128
#define OFF_W2H   81920
#define OFF_W1    115712     // 8 warps * 2 bufs * 5120
#define SMEM_TOTAL 197632

#define XPB    528           // x / W2 plane pitch (bytes)
#define XLOFF  16896u
#define W1PB   80            // W1 row pitch (bytes)
#define W1PLANE 2560         // 32 rows * 80
#define W1BUF   5120         // hi+lo
#define W1WARP  10240        // 2 buffers

__device__ __nv_bfloat16 g_W1h[(size_t)NS_ * NL_ * NL_];
__device__ __nv_bfloat16 g_W1l[(size_t)NS_ * NL_ * NL_];
__device__ __nv_bfloat16 g_W2h[(size_t)NS_ * NO_ * NL_];
__device__ __nv_bfloat16 g_W2l[(size_t)NS_ * NO_ * NL_];

__device__ __forceinline__ void cp16g(uint32_t dst, const void* src) {
    asm volatile("cp.async.cg.shared.global [%0], [%1], 16;" :: "r"(dst), "l"(src) : "memory");
}
#define CPCOMMIT() asm volatile("cp.async.commit_group;" ::: "memory")
#define CPWAIT0()  asm volatile("cp.async.wait_group 0;" ::: "memory")
#define CPWAIT1()  asm volatile("cp.async.wait_group 1;" ::: "memory")

__device__ __forceinline__ void ldm4(uint32_t a, uint32_t* r) {
    asm volatile("ldmatrix.sync.aligned.m8n8.x4.shared.b16 {%0,%1,%2,%3}, [%4];"
                 : "=r"(r[0]), "=r"(r[1]), "=r"(r[2]), "=r"(r[3]) : "r"(a));
}
__device__ __forceinline__ void mma16816(float* d, const uint32_t* a, uint32_t b0, uint32_t b1) {
    asm volatile("mma.sync.aligned.m16n8k16.row.col.f32.bf16.bf16.f32 "
                 "{%0,%1,%2,%3}, {%4,%5,%6,%7}, {%8,%9}, {%0,%1,%2,%3};"
                 : "+f"(d[0]), "+f"(d[1]), "+f"(d[2]), "+f"(d[3])
                 : "r"(a[0]), "r"(a[1]), "r"(a[2]), "r"(a[3]), "r"(b0), "r"(b1));
}
__device__ __forceinline__ float tanh_acc(float x) {
    float xc = fminf(fmaxf(x, -15.f), 15.f);
    float e = __expf(2.f * xc);
    return __fdividef(e - 1.f, e + 1.f);
}
__device__ __forceinline__ void pack2(float f0, float f1, uint32_t& hp, uint32_t& lp) {
    asm("cvt.rn.bf16x2.f32 %0, %1, %2;" : "=r"(hp) : "f"(f1), "f"(f0));
    float h0 = __uint_as_float(hp << 16);
    float h1 = __uint_as_float(hp & 0xffff0000u);
    asm("cvt.rn.bf16x2.f32 %0, %1, %2;" : "=r"(lp) : "f"(f1 - h1), "f"(f0 - h0));
}

// Per-warp W1 slice: compute warp w stages its 32 n-rows x 32 k (hi+lo) of chunk ck.
// 256 x 16B granules -> 8 per lane.
__device__ __forceinline__ void stage_w1_warp(uint32_t s0, int w, int buf, int s, int ck, int lane) {
    uint32_t base = s0 + OFF_W1 + (uint32_t)(w * W1WARP + buf * W1BUF);
    #pragma unroll
    for (int q = 0; q < 8; ++q) {
        int idx = q * 32 + lane;          // 0..255
        int pl = idx >> 7;
        int rem = idx & 127;
        int n = rem >> 2, slot = rem & 3;
        uint32_t d = base + (uint32_t)(pl * W1PLANE + n * W1PB + slot * 16);
        const __nv_bfloat16* p = (pl ? g_W1l : g_W1h)
                               + (size_t)(s * NL_ + w * 32 + n) * NL_ + ck * 32 + slot * 8;
        cp16g(d, p);
    }
    CPCOMMIT();
}
// Stage W2[s] hi+lo from the 2 IO warps (64 threads, 32 granules each).
__device__ __forceinline__ void stage_w2_io(uint32_t s0, int s, int tio) {
    #pragma unroll
    for (int q = 0; q < 32; ++q) {
        int g = tio + 64 * q;             // 0..2047
        int pl = g >> 10;
        int rem = g & 1023;
        int n = rem >> 5, slot = rem & 31;
        uint32_t d = s0 + (uint32_t)(OFF_W2H + pl * XLOFF + n * XPB + slot * 16);
        const __nv_bfloat16* p = (pl ? g_W2l : g_W2h) + (size_t)(s * NO_ + n) * NL_ + slot * 8;
        cp16g(d, p);
    }
    CPCOMMIT();
}

__global__ void cvt_kernel(const float* __restrict__ W1, const float* __restrict__ W2) {
    size_t i = (size_t)blockIdx.x * blockDim.x + threadIdx.x;
    if (i < (size_t)NS_ * NL_ * NL_) {
        float x = W1[i];
        __nv_bfloat16 h = __float2bfloat16(x);
        g_W1h[i] = h;
        g_W1l[i] = __float2bfloat16(x - __bfloat162float(h));
    }
    if (i < (size_t)NS_ * NO_ * NL_) {
        float x = W2[i];
        __nv_bfloat16 h = __float2bfloat16(x);
        g_W2h[i] = h;
        g_W2l[i] = __float2bfloat16(x - __bfloat162float(h));
    }
}

__global__ __launch_bounds__(NTH_, 1)
void lalr_hmma_kernel(const float* __restrict__ latent0,
                      const float* __restrict__ b1,
                      const float* __restrict__ b2,
                      const int*   __restrict__ state_seq,
                      const int*   __restrict__ out_idx,
                      float*       __restrict__ out)
{
    extern __shared__ char smc[];
    const uint32_t s0 = (uint32_t)__cvta_generic_to_shared(smc);
    const int tid  = threadIdx.x;
    const int w    = tid >> 5;
    const int lane = tid & 31;
    const int r0   = blockIdx.x * ROWS_;
    const bool is_io = (w >= 8);

    int*   seq  = (int*)(smc + OFF_SEQ);
    float* ylog = (float*)(smc + OFF_YLOG);   // pitch 36 floats
    float* yb   = (float*)(smc + OFF_YB);     // pitch 68 floats

    const int wn = w * 32;                    // compute warp n-slice base

    const int a_row = (lane & 7) + ((lane >> 3) & 1) * 8;
    const int a_kof = (lane >> 4) * 8;
    const int b_row = (lane & 7) + ((lane >> 4) & 1) * 8;
    const int b_kof = ((lane >> 3) & 1) * 8;

    if (tid < T_) seq[tid] = state_seq[tid];

    if (!is_io) {
        // initial latent -> X0 planes (bf16 hi/lo). 256 threads: 8 thr/row, 32 cols each.
        int r = tid >> 3;
        int cb = (tid & 7) * 32;
        const float2* src = (const float2*)(latent0 + (size_t)(r0 + r) * NL_ + cb);
        #pragma unroll
        for (int i = 0; i < 16; ++i) {
            float2 f = src[i];
            uint32_t hp, lp;
            pack2(f.x, f.y, hp, lp);
            *(uint32_t*)(smc + OFF_X0H + r * XPB + (cb + 2 * i) * 2) = hp;
            *(uint32_t*)(smc + OFF_X0H + XLOFF + r * XPB + (cb + 2 * i) * 2) = lp;
        }
        int sfirst = state_seq[0];
        stage_w1_warp(s0, w, 0, sfirst, 0, lane);
        stage_w1_warp(s0, w, 1, sfirst, 1, lane);
    } else {
        stage_w2_io(s0, state_seq[0], (w - 8) * 32 + lane);
    }
    __syncthreads();

    uint32_t xc = OFF_X0H;
    uint32_t xn = OFF_X1H;

    for (int t = 0; t < T_; ++t) {
        const int s = seq[t];

        if (!is_io) {
            // -------- Phase 1: x @ W1^T, m32 x n32 per warp, term-major order -----
            float acc[2][4][4];
            #pragma unroll
            for (int mt = 0; mt < 2; ++mt)
                #pragma unroll
                for (int nt = 0; nt < 4; ++nt)
                    #pragma unroll
                    for (int i = 0; i < 4; ++i) acc[mt][nt][i] = 0.f;

            const uint32_t wbase = s0 + OFF_W1 + (uint32_t)(w * W1WARP);

            #pragma unroll
            for (int c = 0; c < 8; ++c) {
                if (c == 7) CPWAIT0(); else CPWAIT1();
                __syncwarp();

                const uint32_t wb = wbase + (uint32_t)((c & 1) * W1BUF);

                #pragma unroll
                for (int ks = 0; ks < 2; ++ks) {
                    int gk = c * 32 + ks * 16;
                    int ck2 = ks * 16;
                    uint32_t ah[2][4], al[2][4];
                    ldm4(s0 + xc + (uint32_t)(a_row * XPB + (gk + a_kof) * 2), ah[0]);
                    ldm4(s0 + xc + (uint32_t)((16 + a_row) * XPB + (gk + a_kof) * 2), ah[1]);
                    ldm4(s0 + xc + XLOFF + (uint32_t)(a_row * XPB + (gk + a_kof) * 2), al[0]);
                    ldm4(s0 + xc + XLOFF + (uint32_t)((16 + a_row) * XPB + (gk + a_kof) * 2), al[1]);
                    uint32_t bh[8], bl[8];
                    uint32_t baddr = wb + (uint32_t)(b_row * W1PB + (ck2 + b_kof) * 2);
                    ldm4(baddr, bh);
                    ldm4(baddr + 16 * W1PB, bh + 4);
                    ldm4(baddr + W1PLANE, bl);
                    ldm4(baddr + W1PLANE + 16 * W1PB, bl + 4);
                    // term-major: same-acc reuse distance = 8 MMAs
                    #pragma unroll
                    for (int mt = 0; mt < 2; ++mt)
                        #pragma unroll
                        for (int nt = 0; nt < 4; ++nt)
                            mma16816(acc[mt][nt], ah[mt], bh[2 * nt], bh[2 * nt + 1]);
                    #pragma unroll
                    for (int mt = 0; mt < 2; ++mt)
                        #pragma unroll
                        for (int nt = 0; nt < 4; ++nt)
                            mma16816(acc[mt][nt], al[mt], bh[2 * nt], bh[2 * nt + 1]);
                    #pragma unroll
                    for (int mt = 0; mt < 2; ++mt)
                        #pragma unroll
                        for (int nt = 0; nt < 4; ++nt)
                            mma16816(acc[mt][nt], ah[mt], bl[2 * nt], bl[2 * nt + 1]);
                }

                if (c < 6) {
                    stage_w1_warp(s0, w, c & 1, s, c + 2, lane);
                } else if (c == 7) {
                    int sn = (t < T_ - 1) ? seq[t + 1] : s;
                    stage_w1_warp(s0, w, 0, sn, 0, lane);
                    stage_w1_warp(s0, w, 1, sn, 1, lane);
                }
            }

            // Epilogue: tanh(acc + b1) -> xn planes (warp's own n-columns)
            {
                int rowa = lane >> 2;
                #pragma unroll
                for (int mt = 0; mt < 2; ++mt) {
                    #pragma unroll
                    for (int nt = 0; nt < 4; ++nt) {
                        int colb = wn + nt * 8 + 2 * (lane & 3);
                        float2 bb = __ldg((const float2*)(b1 + s * NL_ + colb));
                        int ra = mt * 16 + rowa;
                        uint32_t hp, lp;
                        pack2(tanh_acc(acc[mt][nt][0] + bb.x), tanh_acc(acc[mt][nt][1] + bb.y), hp, lp);
                        *(uint32_t*)(smc + xn + ra * XPB + colb * 2) = hp;
                        *(uint32_t*)(smc + xn + XLOFF + ra * XPB + colb * 2) = lp;
                        pack2(tanh_acc(acc[mt][nt][2] + bb.x), tanh_acc(acc[mt][nt][3] + bb.y), hp, lp);
                        *(uint32_t*)(smc + xn + (ra + 8) * XPB + colb * 2) = hp;
                        *(uint32_t*)(smc + xn + XLOFF + (ra + 8) * XPB + colb * 2) = lp;
                    }
                }
            }
        }
        __syncthreads();   // BAR: x_new complete, visible to everyone

        if (is_io) {
            // -------- IO warps: phase2 + softmax + scatter + store (overlaps next phase1)
            const int wio = w - 8;
            const int mb  = wio * 16;
            float* sb2p  = (float*)(smc + OFF_SB2)  + wio * 32;
            int*   sidxp = (int*)(smc + OFF_SIDX)   + wio * 32;
            sb2p[lane]  = b2[s * NO_ + lane];
            sidxp[lane] = out_idx[s * NO_ + lane];

            CPWAIT0();       // W2[s] resident (staged by these warps last step)
            __syncwarp();

            float acc[4][4];
            #pragma unroll
            for (int nt = 0; nt < 4; ++nt)
                #pragma unroll
                for (int i = 0; i < 4; ++i) acc[nt][i] = 0.f;

            #pragma unroll
            for (int ks = 0; ks < 16; ++ks) {
                int gk = ks * 16;
                uint32_t ah[4], al[4];
                ldm4(s0 + xn + (uint32_t)((mb + a_row) * XPB + (gk + a_kof) * 2), ah);
                ldm4(s0 + xn + XLOFF + (uint32_t)((mb + a_row) * XPB + (gk + a_kof) * 2), al);
                #pragma unroll
                for (int ns = 0; ns < 2; ++ns) {
                    uint32_t bh[4], bl[4];
                    uint32_t baddr = s0 + (uint32_t)(OFF_W2H
                                   + (ns * 16 + b_row) * XPB + (gk + b_kof) * 2);
                    ldm4(baddr, bh);
                    ldm4(baddr + XLOFF, bl);
                    mma16816(acc[2 * ns],     ah, bh[0], bh[1]);
                    mma16816(acc[2 * ns + 1], ah, bh[2], bh[3]);
                    mma16816(acc[2 * ns],     al, bh[0], bh[1]);
                    mma16816(acc[2 * ns + 1], al, bh[2], bh[3]);
                    mma16816(acc[2 * ns],     ah, bl[0], bl[1]);
                    mma16816(acc[2 * ns + 1], ah, bl[2], bl[3]);
                }
            }

            // Both IO warps' W2 reads done before restaging W2
            asm volatile("bar.sync 1, 64;" ::: "memory");

            // logits -> warp-private ylog rows
            {
                int rowa = mb + (lane >> 2);
                #pragma unroll
                for (int nt = 0; nt < 4; ++nt) {
                    int colb = nt * 8 + 2 * (lane & 3);
                    *(float2*)(ylog + rowa * 36 + colb)       = make_float2(acc[nt][0], acc[nt][1]);
                    *(float2*)(ylog + (rowa + 8) * 36 + colb) = make_float2(acc[nt][2], acc[nt][3]);
                }
            }
            __syncwarp();

            if (lane < 16) {
                int r = mb + lane;
                float lg[32];
                float m = -1e30f;
                #pragma unroll
                for (int o = 0; o < 32; ++o) {
                    lg[o] = ylog[r * 36 + o] + sb2p[o];
                    m = fmaxf(m, lg[o]);
                }
                float ssum = 0.f;
                #pragma unroll
                for (int o = 0; o < 32; ++o) { lg[o] = __expf(lg[o] - m); ssum += lg[o]; }
                float inv = __frcp_rn(ssum);
                float* yrow = yb + r * 68;
                #pragma unroll
                for (int q4 = 0; q4 < 16; ++q4)
                    *(float4*)(yrow + 4 * q4) = make_float4(0.f, 0.f, 0.f, 0.f);
                #pragma unroll
                for (int o = 0; o < 32; ++o)
                    yrow[sidxp[o]] = lg[o] * inv;      // ascending o -> last wins
                float* orow = out + ((size_t)(r0 + r) * T_ + t) * V_;
                #pragma unroll
                for (int q4 = 0; q4 < 16; ++q4)
                    *(float4*)(orow + 4 * q4) = *(const float4*)(yrow + 4 * q4);
            }

            // stage W2 for next step
            int sn = (t < T_ - 1) ? seq[t + 1] : s;
            stage_w2_io(s0, sn, wio * 32 + lane);
        }

        uint32_t tmp = xc; xc = xn; xn = tmp;
    }
}

extern "C" void kernel_launch(void* const* d_in, const int* in_sizes, int n_in,
                              void* d_out, int out_size)
{
    const float* latent0   = (const float*)d_in[0];
    const float* W1        = (const float*)d_in[1];
    const float* b1        = (const float*)d_in[2];
    const float* W2        = (const float*)d_in[3];
    const float* b2        = (const float*)d_in[4];
    const int*   state_seq = (const int*)  d_in[5];
    const int*   out_idx   = (const int*)  d_in[6];
    float*       out       = (float*)      d_out;

    cvt_kernel<<<(int)(((size_t)NS_ * NL_ * NL_ + 255) / 256), 256>>>(W1, W2);

    cudaFuncSetAttribute(lalr_hmma_kernel,
                         cudaFuncAttributeMaxDynamicSharedMemorySize, SMEM_TOTAL);
    lalr_hmma_kernel<<<GRID_, NTH_, SMEM_TOTAL>>>(latent0, b1, b2, state_seq, out_idx, out);
}